// round 3
// baseline (speedup 1.0000x reference)
#include <cuda_runtime.h>
#include <cstdint>

#define NMAX    50000
#define EMAX    800000
#define INDIM   100
#define D1      512
#define D2      256
#define D3      128
#define D4      200

typedef unsigned long long ull;

// Scratch
__device__ float g_dinv[NMAX];
__device__ int   g_group[NMAX];
__device__ float g_gcnt[4];
__device__ float g_gsum[4 * D4];
__device__ int   g_cnt[NMAX];
__device__ int   g_fill[NMAX];
__device__ int   g_rowptr[NMAX + 1];
__device__ int   g_csr[EMAX];
__device__ float g_bufA[(size_t)NMAX * 256];
__device__ float g_bufB[(size_t)NMAX * 256];
__device__ float g_bufC[(size_t)NMAX * 512];

// f32x2 packed helpers
__device__ __forceinline__ ull pack2(float x, float y) {
    ull r; asm("mov.b64 %0, {%1, %2};" : "=l"(r) : "f"(x), "f"(y)); return r;
}
__device__ __forceinline__ void fma2(ull& d, ull a, ull b) {
    asm("fma.rn.f32x2 %0, %1, %2, %0;" : "+l"(d) : "l"(a), "l"(b));
}
__device__ __forceinline__ float2 unpack2(ull v) {
    float2 f; asm("mov.b64 {%0, %1}, %2;" : "=f"(f.x), "=f"(f.y) : "l"(v)); return f;
}

// ---------------------------------------------------------------------------
__global__ void zero_kernel(int M) {
    int i = blockIdx.x * blockDim.x + threadIdx.x;
    if (i < M) { g_cnt[i] = 0; g_fill[i] = 0; }
    if (i < 4 * D4) g_gsum[i] = 0.0f;
    if (i < 4) g_gcnt[i] = 0.0f;
}

__global__ void count_kernel(const int* __restrict__ ei, int E) {
    int e = blockIdx.x * blockDim.x + threadIdx.x;
    if (e >= E) return;
    atomicAdd(&g_cnt[ei[E + e]], 1);
}

// single-block chunked Hillis-Steele scan -> exclusive rowptr
__global__ void scan_kernel(int M) {
    __shared__ int buf[2][1024];
    __shared__ int carry;
    int t = threadIdx.x;
    if (t == 0) { carry = 0; g_rowptr[0] = 0; }
    __syncthreads();
    for (int base = 0; base < M; base += 1024) {
        int i = base + t;
        int v = (i < M) ? g_cnt[i] : 0;
        int sel = 0;
        buf[0][t] = v;
        __syncthreads();
        #pragma unroll
        for (int off = 1; off < 1024; off <<= 1) {
            int x = buf[sel][t];
            if (t >= off) x += buf[sel][t - off];
            buf[sel ^ 1][t] = x;
            sel ^= 1;
            __syncthreads();
        }
        if (i < M) g_rowptr[i + 1] = carry + buf[sel][t];
        int total = buf[sel][1023];
        __syncthreads();
        if (t == 0) carry += total;
        __syncthreads();
    }
}

__global__ void fill_kernel(const int* __restrict__ ei, int E) {
    int e = blockIdx.x * blockDim.x + threadIdx.x;
    if (e >= E) return;
    int d = ei[E + e];
    int pos = atomicAdd(&g_fill[d], 1);
    g_csr[g_rowptr[d] + pos] = ei[e];
}

// warp-per-node: coalesced group classification + dinv
__global__ void node_prep(const float* __restrict__ x, const float* __restrict__ nf, int M) {
    int warp = (blockIdx.x * blockDim.x + threadIdx.x) >> 5;
    int lane = threadIdx.x & 31;
    if (warp >= M) return;
    const float* row = x + (size_t)warp * INDIM;
    bool e0 = true, e1 = true, e2 = true;
    #pragma unroll
    for (int j = lane; j < INDIM; j += 32) {
        float a = row[j];
        e0 = e0 && (a == nf[j]);
        e1 = e1 && (a == nf[INDIM + j]);
        e2 = e2 && (a == nf[2 * INDIM + j]);
    }
    unsigned m = 0xFFFFFFFFu;
    bool a0 = __all_sync(m, e0);
    bool a1 = __all_sync(m, e1);
    bool a2 = __all_sync(m, e2);
    if (lane == 0) {
        int g = a0 ? 0 : (a1 ? 3 : (a2 ? 1 : 2));
        g_group[warp] = g;
        atomicAdd(&g_gcnt[g], 1.0f);
        g_dinv[warp] = rsqrtf((float)(g_rowptr[warp + 1] - g_rowptr[warp] + 1));
    }
}

// bufA = x * dinv[row]
__global__ void scale_x(const float* __restrict__ x, float* __restrict__ out, int M) {
    size_t idx = (size_t)blockIdx.x * blockDim.x + threadIdx.x;
    size_t total = (size_t)M * INDIM;
    if (idx >= total) return;
    int r = (int)(idx / INDIM);
    out[idx] = x[idx] * g_dinv[r];
}

// ---------------------------------------------------------------------------
// Gather aggregation: one warp per dst node.
// epi 0: out = dinv*acc ; epi 1: relu(dinv*acc+b) ; epi 2: relu(dinv*acc+b)*dinv
__global__ __launch_bounds__(256) void gather_kernel(
    const float* __restrict__ Hs, float* __restrict__ out,
    const float* __restrict__ bias, int M, int dim, int epi)
{
    int warp = (blockIdx.x * blockDim.x + threadIdx.x) >> 5;
    int lane = threadIdx.x & 31;
    if (warp >= M) return;
    int d4 = dim >> 2;
    int c0 = lane, c1 = lane + 32;
    bool p0 = c0 < d4, p1 = c1 < d4;
    int start = g_rowptr[warp], end = g_rowptr[warp + 1];
    float di = g_dinv[warp];

    float4 a0 = make_float4(0.f, 0.f, 0.f, 0.f);
    float4 a1 = make_float4(0.f, 0.f, 0.f, 0.f);
    const float* self = Hs + (size_t)warp * dim;
    if (p0) a0 = *(const float4*)(self + c0 * 4);
    if (p1) a1 = *(const float4*)(self + c1 * 4);

    int j = start;
    for (; j + 4 <= end; j += 4) {
        int s0 = g_csr[j], s1 = g_csr[j + 1], s2 = g_csr[j + 2], s3 = g_csr[j + 3];
        const float* r0 = Hs + (size_t)s0 * dim;
        const float* r1 = Hs + (size_t)s1 * dim;
        const float* r2 = Hs + (size_t)s2 * dim;
        const float* r3 = Hs + (size_t)s3 * dim;
        if (p0) {
            float4 v0 = *(const float4*)(r0 + c0 * 4);
            float4 v1 = *(const float4*)(r1 + c0 * 4);
            float4 v2 = *(const float4*)(r2 + c0 * 4);
            float4 v3 = *(const float4*)(r3 + c0 * 4);
            a0.x += v0.x + v1.x + v2.x + v3.x;
            a0.y += v0.y + v1.y + v2.y + v3.y;
            a0.z += v0.z + v1.z + v2.z + v3.z;
            a0.w += v0.w + v1.w + v2.w + v3.w;
        }
        if (p1) {
            float4 v0 = *(const float4*)(r0 + c1 * 4);
            float4 v1 = *(const float4*)(r1 + c1 * 4);
            float4 v2 = *(const float4*)(r2 + c1 * 4);
            float4 v3 = *(const float4*)(r3 + c1 * 4);
            a1.x += v0.x + v1.x + v2.x + v3.x;
            a1.y += v0.y + v1.y + v2.y + v3.y;
            a1.z += v0.z + v1.z + v2.z + v3.z;
            a1.w += v0.w + v1.w + v2.w + v3.w;
        }
    }
    for (; j < end; j++) {
        int s = g_csr[j];
        const float* r = Hs + (size_t)s * dim;
        if (p0) {
            float4 v = *(const float4*)(r + c0 * 4);
            a0.x += v.x; a0.y += v.y; a0.z += v.z; a0.w += v.w;
        }
        if (p1) {
            float4 v = *(const float4*)(r + c1 * 4);
            a1.x += v.x; a1.y += v.y; a1.z += v.z; a1.w += v.w;
        }
    }

    float* orow = out + (size_t)warp * dim;
    if (p0) {
        float4 v;
        v.x = di * a0.x; v.y = di * a0.y; v.z = di * a0.z; v.w = di * a0.w;
        if (epi >= 1) {
            float4 b = *(const float4*)(bias + c0 * 4);
            v.x = fmaxf(v.x + b.x, 0.f); v.y = fmaxf(v.y + b.y, 0.f);
            v.z = fmaxf(v.z + b.z, 0.f); v.w = fmaxf(v.w + b.w, 0.f);
            if (epi == 2) { v.x *= di; v.y *= di; v.z *= di; v.w *= di; }
        }
        *(float4*)(orow + c0 * 4) = v;
    }
    if (p1) {
        float4 v;
        v.x = di * a1.x; v.y = di * a1.y; v.z = di * a1.z; v.w = di * a1.w;
        if (epi >= 1) {
            float4 b = *(const float4*)(bias + c1 * 4);
            v.x = fmaxf(v.x + b.x, 0.f); v.y = fmaxf(v.y + b.y, 0.f);
            v.z = fmaxf(v.z + b.z, 0.f); v.w = fmaxf(v.w + b.w, 0.f);
            if (epi == 2) { v.x *= di; v.y *= di; v.z *= di; v.w *= di; }
        }
        *(float4*)(orow + c1 * 4) = v;
    }
}

// ---------------------------------------------------------------------------
// SGEMM 128x128 tile, 8x8 micro-tile, packed f32x2 FMAs, 256 threads.
// epi 0: C = relu(acc + bias) ; epi 1: C = dinv[row] * acc
__global__ __launch_bounds__(256, 2) void gemm_kernel(
    const float* __restrict__ A, const float* __restrict__ W,
    const float* __restrict__ bias, float* __restrict__ C,
    int M, int K, int N, int epi)
{
    __shared__ float As[16][128];
    __shared__ float Bs[16][128];

    int tid = threadIdx.x;
    int r0 = blockIdx.x * 128;
    int n0 = blockIdx.y * 128;
    int tx = tid & 15, ty = tid >> 4;

    int lar = tid >> 1;          // 0..127 (A row in tile)
    int lak = (tid & 1) * 4;     // 0 or 4; second load at +8
    int lbk = tid >> 4;          // 0..15 (B k row)
    int lbn = (tid & 15) * 8;    // B col offset; two float4s

    ull acc[8][4];
    #pragma unroll
    for (int i = 0; i < 8; i++)
        #pragma unroll
        for (int jp = 0; jp < 4; jp++) acc[i][jp] = 0ull;

    for (int kt = 0; kt < K; kt += 16) {
        // load A tile (transposed into As[k][m])
        #pragma unroll
        for (int h = 0; h < 2; h++) {
            int kg = kt + lak + h * 8;
            int r = r0 + lar;
            float4 a = make_float4(0.f, 0.f, 0.f, 0.f);
            if (r < M) {
                if (kg + 3 < K) {
                    a = *(const float4*)(A + (size_t)r * K + kg);
                } else {
                    const float* ap = A + (size_t)r * K;
                    if (kg + 0 < K) a.x = ap[kg + 0];
                    if (kg + 1 < K) a.y = ap[kg + 1];
                    if (kg + 2 < K) a.z = ap[kg + 2];
                    if (kg + 3 < K) a.w = ap[kg + 3];
                }
            }
            int ks = lak + h * 8;
            As[ks + 0][lar] = a.x;
            As[ks + 1][lar] = a.y;
            As[ks + 2][lar] = a.z;
            As[ks + 3][lar] = a.w;
        }
        // load B tile
        #pragma unroll
        for (int h = 0; h < 2; h++) {
            int kb = kt + lbk;
            int nb = n0 + lbn + h * 4;
            float4 b = make_float4(0.f, 0.f, 0.f, 0.f);
            if (kb < K) {
                if (nb + 3 < N) {
                    b = *(const float4*)(W + (size_t)kb * N + nb);
                } else {
                    const float* wp = W + (size_t)kb * N;
                    if (nb + 0 < N) b.x = wp[nb + 0];
                    if (nb + 1 < N) b.y = wp[nb + 1];
                    if (nb + 2 < N) b.z = wp[nb + 2];
                    if (nb + 3 < N) b.w = wp[nb + 3];
                }
            }
            *(float4*)&Bs[lbk][lbn + h * 4] = b;
        }
        __syncthreads();

        #pragma unroll
        for (int k = 0; k < 16; k++) {
            float4 a0 = *(const float4*)&As[k][ty * 8];
            float4 a1 = *(const float4*)&As[k][ty * 8 + 4];
            float4 b0 = *(const float4*)&Bs[k][tx * 8];
            float4 b1 = *(const float4*)&Bs[k][tx * 8 + 4];
            ull bp0 = pack2(b0.x, b0.y);
            ull bp1 = pack2(b0.z, b0.w);
            ull bp2 = pack2(b1.x, b1.y);
            ull bp3 = pack2(b1.z, b1.w);
            float av[8] = {a0.x, a0.y, a0.z, a0.w, a1.x, a1.y, a1.z, a1.w};
            #pragma unroll
            for (int i = 0; i < 8; i++) {
                ull ap = pack2(av[i], av[i]);
                fma2(acc[i][0], ap, bp0);
                fma2(acc[i][1], ap, bp1);
                fma2(acc[i][2], ap, bp2);
                fma2(acc[i][3], ap, bp3);
            }
        }
        __syncthreads();
    }

    // epilogue
    #pragma unroll
    for (int i = 0; i < 8; i++) {
        int r = r0 + ty * 8 + i;
        if (r >= M) continue;
        float di = (epi == 1) ? g_dinv[r] : 0.0f;
        float* crow = C + (size_t)r * N;
        #pragma unroll
        for (int jp = 0; jp < 4; jp++) {
            float2 v = unpack2(acc[i][jp]);
            int n = n0 + tx * 8 + jp * 2;
            if (epi == 0) {
                if (n < N)     crow[n]     = fmaxf(v.x + bias[n], 0.0f);
                if (n + 1 < N) crow[n + 1] = fmaxf(v.y + bias[n + 1], 0.0f);
            } else {
                if (n < N)     crow[n]     = di * v.x;
                if (n + 1 < N) crow[n + 1] = di * v.y;
            }
        }
    }
}

// ---------------------------------------------------------------------------
__global__ void group_reduce(const float* __restrict__ out4, int M) {
    __shared__ float s[4 * D4];
    for (int i = threadIdx.x; i < 4 * D4; i += blockDim.x) s[i] = 0.0f;
    __syncthreads();
    int base = blockIdx.x * 256;
    for (int n = 0; n < 256; n++) {
        int node = base + n;
        if (node >= M) break;
        int g = g_group[node];
        const float* row = out4 + (size_t)node * D4;
        for (int c = threadIdx.x; c < D4; c += blockDim.x)
            s[g * D4 + c] += row[c];
    }
    __syncthreads();
    for (int i = threadIdx.x; i < 4 * D4; i += blockDim.x)
        if (s[i] != 0.0f) atomicAdd(&g_gsum[i], s[i]);
}

__global__ void final_out(float* __restrict__ out) {
    int i = blockIdx.x * blockDim.x + threadIdx.x;
    if (i >= 4 * D4) return;
    float c = g_gcnt[i / D4];
    out[i] = (c > 0.0f) ? g_gsum[i] / c : 0.0f;
}

// ---------------------------------------------------------------------------
static inline int ceil_div(long long a, long long b) { return (int)((a + b - 1) / b); }

extern "C" void kernel_launch(void* const* d_in, const int* in_sizes, int n_in,
                              void* d_out, int out_size) {
    const float* x  = (const float*)d_in[0];
    const float* nf = (const float*)d_in[1];
    const int*   ei = (const int*)d_in[2];
    const float* W1 = (const float*)d_in[3];
    const float* b1 = (const float*)d_in[4];
    const float* W2 = (const float*)d_in[5];
    const float* b2 = (const float*)d_in[6];
    const float* W3 = (const float*)d_in[7];
    const float* b3 = (const float*)d_in[8];
    const float* W4 = (const float*)d_in[9];
    const float* b4 = (const float*)d_in[10];
    float* out = (float*)d_out;

    int M = in_sizes[0] / INDIM;     // 50000
    int E = in_sizes[2] / 2;         // 800000

    float *bufA, *bufB, *bufC;
    cudaGetSymbolAddress((void**)&bufA, g_bufA);
    cudaGetSymbolAddress((void**)&bufB, g_bufB);
    cudaGetSymbolAddress((void**)&bufC, g_bufC);

    const int T = 256;

    // CSR build + node metadata
    zero_kernel<<<ceil_div(M, T), T>>>(M);
    count_kernel<<<ceil_div(E, T), T>>>(ei, E);
    scan_kernel<<<1, 1024>>>(M);
    fill_kernel<<<ceil_div(E, T), T>>>(ei, E);
    node_prep<<<ceil_div(M, 8), T>>>(x, nf, M);

    int gblocks = ceil_div(M, 8);  // 8 warps per block

    // ---- Layer 1
    scale_x<<<ceil_div((long long)M * INDIM, T), T>>>(x, bufA, M);
    gather_kernel<<<gblocks, 256>>>(bufA, bufB, nullptr, M, INDIM, 0);
    {
        dim3 g(ceil_div(M, 128), ceil_div(D1, 128));
        gemm_kernel<<<g, 256>>>(bufB, W1, b1, bufC, M, INDIM, D1, 0);
    }

    // ---- Layer 2
    {
        dim3 g(ceil_div(M, 128), ceil_div(D2, 128));
        gemm_kernel<<<g, 256>>>(bufC, W2, nullptr, bufA, M, D1, D2, 1);
    }
    gather_kernel<<<gblocks, 256>>>(bufA, bufB, b2, M, D2, 1);

    // ---- Layer 3
    {
        dim3 g(ceil_div(M, 128), ceil_div(D3, 128));
        gemm_kernel<<<g, 256>>>(bufB, W3, nullptr, bufA, M, D2, D3, 1);
    }
    gather_kernel<<<gblocks, 256>>>(bufA, bufB, b3, M, D3, 2);

    // ---- Layer 4
    gather_kernel<<<gblocks, 256>>>(bufB, bufA, nullptr, M, D3, 0);
    {
        dim3 g(ceil_div(M, 128), ceil_div(D4, 128));
        gemm_kernel<<<g, 256>>>(bufA, W4, b4, bufC, M, D3, D4, 0);
    }

    // ---- grouped mean pooling
    group_reduce<<<ceil_div(M, 256), 128>>>(bufC, M);
    final_out<<<ceil_div(4 * D4, T), T>>>(out);
}

// round 4
// speedup vs baseline: 1.0645x; 1.0645x over previous
#include <cuda_runtime.h>
#include <cstdint>

#define NMAX    50000
#define EMAX    800000
#define INDIM   100
#define D1      512
#define D2      256
#define D3      128
#define D4      200

// Scratch
__device__ float g_dinv[NMAX];
__device__ int   g_group[NMAX];
__device__ float g_gcnt[4];
__device__ float g_gsum[4 * D4];
__device__ int   g_cnt[NMAX];
__device__ int   g_fill[NMAX];
__device__ int   g_rowptr[NMAX + 1];
__device__ int   g_csr[EMAX];
__device__ float g_bufA[(size_t)NMAX * 256];
__device__ float g_bufB[(size_t)NMAX * 256];
__device__ float g_bufC[(size_t)NMAX * 512];

// ---------------------------------------------------------------------------
__global__ void zero_kernel(int M) {
    int i = blockIdx.x * blockDim.x + threadIdx.x;
    if (i < M) { g_cnt[i] = 0; g_fill[i] = 0; }
    if (i < 4 * D4) g_gsum[i] = 0.0f;
    if (i < 4) g_gcnt[i] = 0.0f;
}

__global__ void count_kernel(const int* __restrict__ ei, int E) {
    int e = blockIdx.x * blockDim.x + threadIdx.x;
    if (e >= E) return;
    atomicAdd(&g_cnt[ei[E + e]], 1);
}

// single-block chunked Hillis-Steele scan -> exclusive rowptr
__global__ void scan_kernel(int M) {
    __shared__ int buf[2][1024];
    __shared__ int carry;
    int t = threadIdx.x;
    if (t == 0) { carry = 0; g_rowptr[0] = 0; }
    __syncthreads();
    for (int base = 0; base < M; base += 1024) {
        int i = base + t;
        int v = (i < M) ? g_cnt[i] : 0;
        int sel = 0;
        buf[0][t] = v;
        __syncthreads();
        #pragma unroll
        for (int off = 1; off < 1024; off <<= 1) {
            int x = buf[sel][t];
            if (t >= off) x += buf[sel][t - off];
            buf[sel ^ 1][t] = x;
            sel ^= 1;
            __syncthreads();
        }
        if (i < M) g_rowptr[i + 1] = carry + buf[sel][t];
        int total = buf[sel][1023];
        __syncthreads();
        if (t == 0) carry += total;
        __syncthreads();
    }
}

__global__ void fill_kernel(const int* __restrict__ ei, int E) {
    int e = blockIdx.x * blockDim.x + threadIdx.x;
    if (e >= E) return;
    int d = ei[E + e];
    int pos = atomicAdd(&g_fill[d], 1);
    g_csr[g_rowptr[d] + pos] = ei[e];
}

// warp-per-node: coalesced group classification + dinv
__global__ void node_prep(const float* __restrict__ x, const float* __restrict__ nf, int M) {
    int warp = (blockIdx.x * blockDim.x + threadIdx.x) >> 5;
    int lane = threadIdx.x & 31;
    if (warp >= M) return;
    const float* row = x + (size_t)warp * INDIM;
    bool e0 = true, e1 = true, e2 = true;
    #pragma unroll
    for (int j = lane; j < INDIM; j += 32) {
        float a = row[j];
        e0 = e0 && (a == nf[j]);
        e1 = e1 && (a == nf[INDIM + j]);
        e2 = e2 && (a == nf[2 * INDIM + j]);
    }
    unsigned m = 0xFFFFFFFFu;
    bool a0 = __all_sync(m, e0);
    bool a1 = __all_sync(m, e1);
    bool a2 = __all_sync(m, e2);
    if (lane == 0) {
        int g = a0 ? 0 : (a1 ? 3 : (a2 ? 1 : 2));
        g_group[warp] = g;
        atomicAdd(&g_gcnt[g], 1.0f);
        g_dinv[warp] = rsqrtf((float)(g_rowptr[warp + 1] - g_rowptr[warp] + 1));
    }
}

// bufA = x * dinv[row]
__global__ void scale_x(const float* __restrict__ x, float* __restrict__ out, int M) {
    size_t idx = (size_t)blockIdx.x * blockDim.x + threadIdx.x;
    size_t total = (size_t)M * INDIM;
    if (idx >= total) return;
    int r = (int)(idx / INDIM);
    out[idx] = x[idx] * g_dinv[r];
}

// ---------------------------------------------------------------------------
// Gather aggregation: one warp per dst node.
// epi 0: out = dinv*acc ; epi 1: relu(dinv*acc+b) ; epi 2: relu(dinv*acc+b)*dinv
__global__ __launch_bounds__(256) void gather_kernel(
    const float* __restrict__ Hs, float* __restrict__ out,
    const float* __restrict__ bias, int M, int dim, int epi)
{
    int warp = (blockIdx.x * blockDim.x + threadIdx.x) >> 5;
    int lane = threadIdx.x & 31;
    if (warp >= M) return;
    int d4 = dim >> 2;
    int c0 = lane, c1 = lane + 32;
    bool p0 = c0 < d4, p1 = c1 < d4;
    int start = g_rowptr[warp], end = g_rowptr[warp + 1];
    float di = g_dinv[warp];

    float4 a0 = make_float4(0.f, 0.f, 0.f, 0.f);
    float4 a1 = make_float4(0.f, 0.f, 0.f, 0.f);
    const float* self = Hs + (size_t)warp * dim;
    if (p0) a0 = *(const float4*)(self + c0 * 4);
    if (p1) a1 = *(const float4*)(self + c1 * 4);

    int j = start;
    for (; j + 4 <= end; j += 4) {
        int s0 = g_csr[j], s1 = g_csr[j + 1], s2 = g_csr[j + 2], s3 = g_csr[j + 3];
        const float* r0 = Hs + (size_t)s0 * dim;
        const float* r1 = Hs + (size_t)s1 * dim;
        const float* r2 = Hs + (size_t)s2 * dim;
        const float* r3 = Hs + (size_t)s3 * dim;
        if (p0) {
            float4 v0 = *(const float4*)(r0 + c0 * 4);
            float4 v1 = *(const float4*)(r1 + c0 * 4);
            float4 v2 = *(const float4*)(r2 + c0 * 4);
            float4 v3 = *(const float4*)(r3 + c0 * 4);
            a0.x += v0.x + v1.x + v2.x + v3.x;
            a0.y += v0.y + v1.y + v2.y + v3.y;
            a0.z += v0.z + v1.z + v2.z + v3.z;
            a0.w += v0.w + v1.w + v2.w + v3.w;
        }
        if (p1) {
            float4 v0 = *(const float4*)(r0 + c1 * 4);
            float4 v1 = *(const float4*)(r1 + c1 * 4);
            float4 v2 = *(const float4*)(r2 + c1 * 4);
            float4 v3 = *(const float4*)(r3 + c1 * 4);
            a1.x += v0.x + v1.x + v2.x + v3.x;
            a1.y += v0.y + v1.y + v2.y + v3.y;
            a1.z += v0.z + v1.z + v2.z + v3.z;
            a1.w += v0.w + v1.w + v2.w + v3.w;
        }
    }
    for (; j < end; j++) {
        int s = g_csr[j];
        const float* r = Hs + (size_t)s * dim;
        if (p0) {
            float4 v = *(const float4*)(r + c0 * 4);
            a0.x += v.x; a0.y += v.y; a0.z += v.z; a0.w += v.w;
        }
        if (p1) {
            float4 v = *(const float4*)(r + c1 * 4);
            a1.x += v.x; a1.y += v.y; a1.z += v.z; a1.w += v.w;
        }
    }

    float* orow = out + (size_t)warp * dim;
    if (p0) {
        float4 v;
        v.x = di * a0.x; v.y = di * a0.y; v.z = di * a0.z; v.w = di * a0.w;
        if (epi >= 1) {
            float4 b = *(const float4*)(bias + c0 * 4);
            v.x = fmaxf(v.x + b.x, 0.f); v.y = fmaxf(v.y + b.y, 0.f);
            v.z = fmaxf(v.z + b.z, 0.f); v.w = fmaxf(v.w + b.w, 0.f);
            if (epi == 2) { v.x *= di; v.y *= di; v.z *= di; v.w *= di; }
        }
        *(float4*)(orow + c0 * 4) = v;
    }
    if (p1) {
        float4 v;
        v.x = di * a1.x; v.y = di * a1.y; v.z = di * a1.z; v.w = di * a1.w;
        if (epi >= 1) {
            float4 b = *(const float4*)(bias + c1 * 4);
            v.x = fmaxf(v.x + b.x, 0.f); v.y = fmaxf(v.y + b.y, 0.f);
            v.z = fmaxf(v.z + b.z, 0.f); v.w = fmaxf(v.w + b.w, 0.f);
            if (epi == 2) { v.x *= di; v.y *= di; v.z *= di; v.w *= di; }
        }
        *(float4*)(orow + c1 * 4) = v;
    }
}

// ---------------------------------------------------------------------------
// Split-TF32 tensor-core GEMM. C[M,N] = A[M,K] @ W[K,N] with fp32-class accuracy.
// Block tile 128x128, 8 warps (warp tile 32x64), m16n8k8 tf32 MMA,
// 3-term compensation: ahi*bhi + ahi*blo + alo*bhi.
// epi 0: C = relu(acc + bias) ; epi 1: C = dinv[row] * acc

__device__ __forceinline__ void tf32_split(float v, float& hi, float& lo) {
    unsigned h;
    asm("cvt.rna.tf32.f32 %0, %1;" : "=r"(h) : "f"(v));
    hi = __uint_as_float(h);
    float r = v - hi;
    unsigned l;
    asm("cvt.rna.tf32.f32 %0, %1;" : "=r"(l) : "f"(r));
    lo = __uint_as_float(l);
}

__device__ __forceinline__ void mma_tf32(float* c, const float* a, const float* b) {
    asm volatile(
        "mma.sync.aligned.m16n8k8.row.col.f32.tf32.tf32.f32 "
        "{%0,%1,%2,%3}, {%4,%5,%6,%7}, {%8,%9}, {%0,%1,%2,%3};\n"
        : "+f"(c[0]), "+f"(c[1]), "+f"(c[2]), "+f"(c[3])
        : "r"(__float_as_uint(a[0])), "r"(__float_as_uint(a[1])),
          "r"(__float_as_uint(a[2])), "r"(__float_as_uint(a[3])),
          "r"(__float_as_uint(b[0])), "r"(__float_as_uint(b[1])));
}

__global__ __launch_bounds__(256) void gemm_tc(
    const float* __restrict__ A, const float* __restrict__ W,
    const float* __restrict__ bias, float* __restrict__ C,
    int M, int K, int N, int epi)
{
    __shared__ float As_hi[2][8][132], As_lo[2][8][132];
    __shared__ float Bs_hi[2][8][132], Bs_lo[2][8][132];

    int tid = threadIdx.x;
    int r0 = blockIdx.x * 128;
    int n0 = blockIdx.y * 128;

    int wid = tid >> 5, lane = tid & 31;
    int g = lane >> 2, t = lane & 3;
    int mbase = (wid >> 1) * 32;   // warp row base within tile
    int nbase = (wid & 1) * 64;    // warp col base within tile

    // loader indices
    int la_r = tid >> 1;            // 0..127
    int la_k = (tid & 1) * 4;       // 0 or 4
    int lb_k = tid >> 5;            // 0..7
    int lb_n = (tid & 31) * 4;      // 0..124

    float acc[2][8][4];
    #pragma unroll
    for (int mi = 0; mi < 2; mi++)
        #pragma unroll
        for (int ni = 0; ni < 8; ni++)
            #pragma unroll
            for (int q = 0; q < 4; q++) acc[mi][ni][q] = 0.0f;

    int nk = (K + 7) >> 3;
    float4 aR, bR;

    // ---- prefetch tile 0
    {
        int kg = la_k;
        int r = r0 + la_r;
        aR = make_float4(0.f, 0.f, 0.f, 0.f);
        if (r < M) {
            const float* ap = A + (size_t)r * K;
            if (kg + 3 < K) aR = *(const float4*)(ap + kg);
            else {
                if (kg + 0 < K) aR.x = ap[kg + 0];
                if (kg + 1 < K) aR.y = ap[kg + 1];
                if (kg + 2 < K) aR.z = ap[kg + 2];
                if (kg + 3 < K) aR.w = ap[kg + 3];
            }
        }
        int kb = lb_k, nb = n0 + lb_n;
        bR = make_float4(0.f, 0.f, 0.f, 0.f);
        if (kb < K) {
            const float* wp = W + (size_t)kb * N;
            if (nb + 3 < N) bR = *(const float4*)(wp + nb);
            else {
                if (nb + 0 < N) bR.x = wp[nb + 0];
                if (nb + 1 < N) bR.y = wp[nb + 1];
                if (nb + 2 < N) bR.z = wp[nb + 2];
                if (nb + 3 < N) bR.w = wp[nb + 3];
            }
        }
    }
    // store tile 0 into stage 0
    {
        float av[4] = {aR.x, aR.y, aR.z, aR.w};
        #pragma unroll
        for (int i = 0; i < 4; i++) {
            float hi, lo; tf32_split(av[i], hi, lo);
            As_hi[0][la_k + i][la_r] = hi;
            As_lo[0][la_k + i][la_r] = lo;
        }
        float bv[4] = {bR.x, bR.y, bR.z, bR.w};
        #pragma unroll
        for (int i = 0; i < 4; i++) {
            float hi, lo; tf32_split(bv[i], hi, lo);
            Bs_hi[0][lb_k][lb_n + i] = hi;
            Bs_lo[0][lb_k][lb_n + i] = lo;
        }
    }
    __syncthreads();

    int st = 0;
    for (int it = 0; it < nk; it++) {
        // prefetch next tile to regs
        if (it + 1 < nk) {
            int kt = (it + 1) * 8;
            int kg = kt + la_k;
            int r = r0 + la_r;
            aR = make_float4(0.f, 0.f, 0.f, 0.f);
            if (r < M) {
                const float* ap = A + (size_t)r * K;
                if (kg + 3 < K) aR = *(const float4*)(ap + kg);
                else {
                    if (kg + 0 < K) aR.x = ap[kg + 0];
                    if (kg + 1 < K) aR.y = ap[kg + 1];
                    if (kg + 2 < K) aR.z = ap[kg + 2];
                    if (kg + 3 < K) aR.w = ap[kg + 3];
                }
            }
            int kb = kt + lb_k, nb = n0 + lb_n;
            bR = make_float4(0.f, 0.f, 0.f, 0.f);
            if (kb < K) {
                const float* wp = W + (size_t)kb * N;
                if (nb + 3 < N) bR = *(const float4*)(wp + nb);
                else {
                    if (nb + 0 < N) bR.x = wp[nb + 0];
                    if (nb + 1 < N) bR.y = wp[nb + 1];
                    if (nb + 2 < N) bR.z = wp[nb + 2];
                    if (nb + 3 < N) bR.w = wp[nb + 3];
                }
            }
        }

        // ---- compute on stage st
        {
            float ahi[2][4], alo[2][4];
            #pragma unroll
            for (int mi = 0; mi < 2; mi++) {
                int row0 = mbase + mi * 16 + g;
                int row1 = row0 + 8;
                ahi[mi][0] = As_hi[st][t][row0];
                ahi[mi][1] = As_hi[st][t][row1];
                ahi[mi][2] = As_hi[st][t + 4][row0];
                ahi[mi][3] = As_hi[st][t + 4][row1];
                alo[mi][0] = As_lo[st][t][row0];
                alo[mi][1] = As_lo[st][t][row1];
                alo[mi][2] = As_lo[st][t + 4][row0];
                alo[mi][3] = As_lo[st][t + 4][row1];
            }
            float bhi[8][2], blo[8][2];
            #pragma unroll
            for (int ni = 0; ni < 8; ni++) {
                int n = nbase + ni * 8 + g;
                bhi[ni][0] = Bs_hi[st][t][n];
                bhi[ni][1] = Bs_hi[st][t + 4][n];
                blo[ni][0] = Bs_lo[st][t][n];
                blo[ni][1] = Bs_lo[st][t + 4][n];
            }
            #pragma unroll
            for (int mi = 0; mi < 2; mi++)
                #pragma unroll
                for (int ni = 0; ni < 8; ni++)
                    mma_tf32(acc[mi][ni], ahi[mi], bhi[ni]);
            #pragma unroll
            for (int mi = 0; mi < 2; mi++)
                #pragma unroll
                for (int ni = 0; ni < 8; ni++)
                    mma_tf32(acc[mi][ni], ahi[mi], blo[ni]);
            #pragma unroll
            for (int mi = 0; mi < 2; mi++)
                #pragma unroll
                for (int ni = 0; ni < 8; ni++)
                    mma_tf32(acc[mi][ni], alo[mi], bhi[ni]);
        }

        if (it + 1 < nk) {
            __syncthreads();
            int sn = st ^ 1;
            float av[4] = {aR.x, aR.y, aR.z, aR.w};
            #pragma unroll
            for (int i = 0; i < 4; i++) {
                float hi, lo; tf32_split(av[i], hi, lo);
                As_hi[sn][la_k + i][la_r] = hi;
                As_lo[sn][la_k + i][la_r] = lo;
            }
            float bv[4] = {bR.x, bR.y, bR.z, bR.w};
            #pragma unroll
            for (int i = 0; i < 4; i++) {
                float hi, lo; tf32_split(bv[i], hi, lo);
                Bs_hi[sn][lb_k][lb_n + i] = hi;
                Bs_lo[sn][lb_k][lb_n + i] = lo;
            }
            __syncthreads();
        }
        st ^= 1;
    }

    // ---- epilogue
    #pragma unroll
    for (int mi = 0; mi < 2; mi++) {
        int row0 = r0 + mbase + mi * 16 + g;
        int row1 = row0 + 8;
        float d0 = 0.f, d1 = 0.f;
        if (epi == 1) {
            if (row0 < M) d0 = g_dinv[row0];
            if (row1 < M) d1 = g_dinv[row1];
        }
        #pragma unroll
        for (int ni = 0; ni < 8; ni++) {
            int col = n0 + nbase + ni * 8 + 2 * t;
            float* c = acc[mi][ni];
            if (epi == 0) {
                float bx = (col < N) ? bias[col] : 0.f;
                float by = (col + 1 < N) ? bias[col + 1] : 0.f;
                if (row0 < M) {
                    if (col < N)     C[(size_t)row0 * N + col]     = fmaxf(c[0] + bx, 0.f);
                    if (col + 1 < N) C[(size_t)row0 * N + col + 1] = fmaxf(c[1] + by, 0.f);
                }
                if (row1 < M) {
                    if (col < N)     C[(size_t)row1 * N + col]     = fmaxf(c[2] + bx, 0.f);
                    if (col + 1 < N) C[(size_t)row1 * N + col + 1] = fmaxf(c[3] + by, 0.f);
                }
            } else {
                if (row0 < M) {
                    if (col < N)     C[(size_t)row0 * N + col]     = d0 * c[0];
                    if (col + 1 < N) C[(size_t)row0 * N + col + 1] = d0 * c[1];
                }
                if (row1 < M) {
                    if (col < N)     C[(size_t)row1 * N + col]     = d1 * c[2];
                    if (col + 1 < N) C[(size_t)row1 * N + col + 1] = d1 * c[3];
                }
            }
        }
    }
}

// ---------------------------------------------------------------------------
__global__ void group_reduce(const float* __restrict__ out4, int M) {
    __shared__ float s[4 * D4];
    for (int i = threadIdx.x; i < 4 * D4; i += blockDim.x) s[i] = 0.0f;
    __syncthreads();
    int base = blockIdx.x * 256;
    for (int n = 0; n < 256; n++) {
        int node = base + n;
        if (node >= M) break;
        int g = g_group[node];
        const float* row = out4 + (size_t)node * D4;
        for (int c = threadIdx.x; c < D4; c += blockDim.x)
            s[g * D4 + c] += row[c];
    }
    __syncthreads();
    for (int i = threadIdx.x; i < 4 * D4; i += blockDim.x)
        if (s[i] != 0.0f) atomicAdd(&g_gsum[i], s[i]);
}

__global__ void final_out(float* __restrict__ out) {
    int i = blockIdx.x * blockDim.x + threadIdx.x;
    if (i >= 4 * D4) return;
    float c = g_gcnt[i / D4];
    out[i] = (c > 0.0f) ? g_gsum[i] / c : 0.0f;
}

// ---------------------------------------------------------------------------
static inline int ceil_div(long long a, long long b) { return (int)((a + b - 1) / b); }

extern "C" void kernel_launch(void* const* d_in, const int* in_sizes, int n_in,
                              void* d_out, int out_size) {
    const float* x  = (const float*)d_in[0];
    const float* nf = (const float*)d_in[1];
    const int*   ei = (const int*)d_in[2];
    const float* W1 = (const float*)d_in[3];
    const float* b1 = (const float*)d_in[4];
    const float* W2 = (const float*)d_in[5];
    const float* b2 = (const float*)d_in[6];
    const float* W3 = (const float*)d_in[7];
    const float* b3 = (const float*)d_in[8];
    const float* W4 = (const float*)d_in[9];
    const float* b4 = (const float*)d_in[10];
    float* out = (float*)d_out;

    int M = in_sizes[0] / INDIM;     // 50000
    int E = in_sizes[2] / 2;         // 800000

    float *bufA, *bufB, *bufC;
    cudaGetSymbolAddress((void**)&bufA, g_bufA);
    cudaGetSymbolAddress((void**)&bufB, g_bufB);
    cudaGetSymbolAddress((void**)&bufC, g_bufC);

    const int T = 256;

    // CSR build + node metadata
    zero_kernel<<<ceil_div(M, T), T>>>(M);
    count_kernel<<<ceil_div(E, T), T>>>(ei, E);
    scan_kernel<<<1, 1024>>>(M);
    fill_kernel<<<ceil_div(E, T), T>>>(ei, E);
    node_prep<<<ceil_div(M, 8), T>>>(x, nf, M);

    int gblocks = ceil_div(M, 8);  // 8 warps per block

    // ---- Layer 1
    scale_x<<<ceil_div((long long)M * INDIM, T), T>>>(x, bufA, M);
    gather_kernel<<<gblocks, 256>>>(bufA, bufB, nullptr, M, INDIM, 0);
    {
        dim3 g(ceil_div(M, 128), ceil_div(D1, 128));
        gemm_tc<<<g, 256>>>(bufB, W1, b1, bufC, M, INDIM, D1, 0);
    }

    // ---- Layer 2
    {
        dim3 g(ceil_div(M, 128), ceil_div(D2, 128));
        gemm_tc<<<g, 256>>>(bufC, W2, nullptr, bufA, M, D1, D2, 1);
    }
    gather_kernel<<<gblocks, 256>>>(bufA, bufB, b2, M, D2, 1);

    // ---- Layer 3
    {
        dim3 g(ceil_div(M, 128), ceil_div(D3, 128));
        gemm_tc<<<g, 256>>>(bufB, W3, nullptr, bufA, M, D2, D3, 1);
    }
    gather_kernel<<<gblocks, 256>>>(bufA, bufB, b3, M, D3, 2);

    // ---- Layer 4
    gather_kernel<<<gblocks, 256>>>(bufB, bufA, nullptr, M, D3, 0);
    {
        dim3 g(ceil_div(M, 128), ceil_div(D4, 128));
        gemm_tc<<<g, 256>>>(bufA, W4, b4, bufC, M, D3, D4, 0);
    }

    // ---- grouped mean pooling
    group_reduce<<<ceil_div(M, 256), 128>>>(bufC, M);
    final_out<<<ceil_div(4 * D4, T), T>>>(out);
}